// round 10
// baseline (speedup 1.0000x reference)
#include <cuda_runtime.h>
#include <cuda_bf16.h>
#include <cstdint>

// Problem constants
#define NROWS 2048
#define DDIM  9216             // C*KH*KW
#define TBM   128              // gram tile M = N = 128
#define T16   (NROWS / TBM)    // 16 tiles per dim (max)
#define NPAIR (T16 * (T16 + 1) / 2)   // 136 tile-pairs
#define SPLITS 8
#define KCH   (DDIM / SPLITS)  // 1152 k-elems per split
#define BK    64               // k-elems per pipeline stage (one k-block)
#define NIT   (KCH / BK)       // 18 iterations
#define KB_TOT (DDIM / BK)     // 144 k-blocks
#define STAGES 3
#define OPBYTES (TBM * 128)                 // 16 KB per operand per stage
#define STAGE_BYTES (2 * OPBYTES)           // 32 KB
#define DSMEM_BYTES (STAGES * STAGE_BYTES)  // 96 KB

// Device scratch (no allocations allowed)
// g_nf2 layout: [kblock][row][64 bf16], SW128 swizzle baked per 128B row:
// 16B group g of row r lives at byte r*128 + ((g ^ (r & 7)) * 16).
__device__ __align__(16) __nv_bfloat16 g_nf2[(size_t)KB_TOT * NROWS * BK];
__device__ int      g_k;
__device__ float    g_sumsq;
__device__ unsigned g_tile_cnt[NPAIR];
__device__ unsigned g_pairs_done;
__device__ float    g_part[NPAIR * SPLITS][TBM * TBM];  // split-K partial tiles

// ---------------- mbarrier / bulk-copy helpers (base sm_90 PTX) ----------------
#define MBAR_INIT(addr, cnt) \
    asm volatile("mbarrier.init.shared.b64 [%0], %1;" :: "r"(addr), "r"(cnt) : "memory")

#define MBAR_ARRIVE_EXPECT(addr, bytes) \
    asm volatile("mbarrier.arrive.expect_tx.shared.b64 _, [%0], %1;" \
                 :: "r"(addr), "r"(bytes) : "memory")

#define MBAR_WAIT(addr, parity) do {                                              \
    asm volatile("{\n\t.reg .pred P1;\n\t"                                        \
        "WL%=:\n\t"                                                               \
        "mbarrier.try_wait.parity.acquire.cta.shared::cta.b64 P1, [%0], %1, 0x989680;\n\t" \
        "@P1 bra.uni WD%=;\n\t"                                                   \
        "bra.uni WL%=;\n\t"                                                       \
        "WD%=:\n\t}"                                                              \
        :: "r"(addr), "r"(parity) : "memory");                                    \
} while (0)

#define BULK_G2S(dst, src, bytes, mbar) \
    asm volatile("cp.async.bulk.shared::cta.global.mbarrier::complete_tx::bytes " \
                 "[%0], [%1], %2, [%3];" \
                 :: "r"(dst), "l"(src), "r"(bytes), "r"(mbar) : "memory")

// ---------------------------------------------------------------------------
// Kernel 1: per-row normalize + inline mask scan + pad-row zeroing.
// Writes g_nf2 in k-block-major, swizzle-baked layout.
// ---------------------------------------------------------------------------
__global__ void __launch_bounds__(256) normalize_kernel(const float* __restrict__ w,
                                                        const float* __restrict__ mask,
                                                        float* __restrict__ out) {
    __shared__ int s_cnt[32];
    __shared__ int s_posk[2];
    int row = blockIdx.x;
    int tid = threadIdx.x;
    int lane = tid & 31, wid = tid >> 5;
    const unsigned full = 0xffffffffu;

    // inline scan: each thread owns mask[8t .. 8t+7]
    const float4* m4 = (const float4*)mask;
    float4 ma = m4[2 * tid], mb = m4[2 * tid + 1];
    int c8 = (ma.x > 0.5f) + (ma.y > 0.5f) + (ma.z > 0.5f) + (ma.w > 0.5f)
           + (mb.x > 0.5f) + (mb.y > 0.5f) + (mb.z > 0.5f) + (mb.w > 0.5f);
    int incl = c8;
#pragma unroll
    for (int o = 1; o < 32; o <<= 1) {
        int v = __shfl_up_sync(full, incl, o);
        if (lane >= o) incl += v;
    }
    if (lane == 31) s_cnt[wid] = incl;
    __syncthreads();
    if (wid == 0) {
        int iv = (lane < 8) ? s_cnt[lane] : 0;
#pragma unroll
        for (int o = 1; o < 8; o <<= 1) {
            int u = __shfl_up_sync(full, iv, o);
            if (lane >= o) iv += u;
        }
        if (lane < 8) s_cnt[lane] = iv;
    }
    __syncthreads();
    if (tid == (row >> 3)) {
        int exclWarp = (wid > 0) ? s_cnt[wid - 1] : 0;
        int excl8 = exclWarp + incl - c8;
        int base = row & ~7;
        int p = excl8;
        bool act = false;
#pragma unroll
        for (int q = 0; q < 8; q++) {
            int rr = base + q;
            bool a = mask[rr] > 0.5f;
            if (rr < row) p += a;
            else if (rr == row) act = a;
        }
        s_posk[0] = act ? p : -(row - p) - 1;   // inactive: encode inactive index
        s_posk[1] = s_cnt[7];
    }
    __syncthreads();
    int pos = s_posk[0];
    int k   = s_posk[1];

    if (row == 0 && tid < NPAIR) g_tile_cnt[tid] = 0u;
    if (row == 0 && tid == 0) {
        g_k = k; g_sumsq = 0.0f; g_pairs_done = 0u;
        if (k < 2) out[0] = 0.0f;
    }

    uint2* nf2 = (uint2*)g_nf2;   // 8B units; per kb block = NROWS*16 uint2

    if (pos < 0) {
        // zero pad rows [k, ceil(k/128)*128) so gram tiles see exact zeros
        int padIdx = -pos - 1;
        int T = (k + TBM - 1) >> 7;
        int padRows = T * TBM - k;
        if (padIdx < padRows) {
            int prow = k + padIdx;
            uint2 z = make_uint2(0u, 0u);
#pragma unroll
            for (int i = 0; i < 9; i++) {
                int c = tid + i * 256;            // 8B chunk index 0..2303
                int kb = c >> 4, rem = c & 15;
                int g16 = rem >> 1, half = rem & 1;
                size_t idx = (size_t)kb * (NROWS * 16) + (size_t)prow * 16
                           + ((g16 ^ (prow & 7)) << 1) + half;
                nf2[idx] = z;
            }
        }
        return;
    }

    const float4* src = (const float4*)(w + (size_t)row * DDIM);
    float4 v[9];
    float sum = 0.0f, sumsq = 0.0f;
#pragma unroll
    for (int i = 0; i < 9; i++) {
        v[i] = src[tid + i * 256];
        sum   += v[i].x + v[i].y + v[i].z + v[i].w;
        sumsq += v[i].x * v[i].x + v[i].y * v[i].y + v[i].z * v[i].z + v[i].w * v[i].w;
    }

    __shared__ float rs[256], rq[256];
    rs[tid] = sum; rq[tid] = sumsq;
    __syncthreads();
    for (int o = 128; o > 0; o >>= 1) {
        if (tid < o) { rs[tid] += rs[tid + o]; rq[tid] += rq[tid + o]; }
        __syncthreads();
    }
    __shared__ float s_mean, s_inv;
    if (tid == 0) {
        float mean = rs[0] * (1.0f / DDIM);
        float var  = fmaxf(rq[0] * (1.0f / DDIM) - mean * mean, 0.0f);
        float stdv = sqrtf(var);
        s_mean = mean;
        s_inv  = (stdv == 0.0f) ? 1.0f : (1.0f / stdv);
    }
    __syncthreads();
    float mean = s_mean, inv = s_inv;

#pragma unroll
    for (int i = 0; i < 9; i++) {
        __nv_bfloat162 lo = __floats2bfloat162_rn((v[i].x - mean) * inv, (v[i].y - mean) * inv);
        __nv_bfloat162 hi = __floats2bfloat162_rn((v[i].z - mean) * inv, (v[i].w - mean) * inv);
        uint2 o;
        o.x = *(uint32_t*)&lo;
        o.y = *(uint32_t*)&hi;
        int c = tid + i * 256;                // 8B chunk index (4 bf16)
        int kb = c >> 4, rem = c & 15;
        int g16 = rem >> 1, half = rem & 1;
        size_t idx = (size_t)kb * (NROWS * 16) + (size_t)pos * 16
                   + ((g16 ^ (pos & 7)) << 1) + half;
        nf2[idx] = o;
    }
}

// ---------------------------------------------------------------------------
// Kernel 2: 128x128 bf16 Gram via mma.sync, split-K=8, 4 warps with 64x64
// warp tiles (32 independent HMMA per k16 step, minimal LDSM redundancy).
// Stage fed by TWO 16KB cp.async.bulk copies from one thread. 3-stage ring.
// Last split combines partials + squares + finalizes.
// ---------------------------------------------------------------------------
__global__ void __launch_bounds__(128, 2) gram_kernel(float* __restrict__ out) {
    extern __shared__ __align__(16) char smem[];
    __shared__ __align__(8) unsigned long long s_mbar[STAGES];
    __shared__ float s_red[4];
    __shared__ unsigned s_prev;

    int k = g_k;
    int blk = blockIdx.x;
    int pair = blk >> 3;
    int split = blk & 7;
    int bi = 0, rem = pair;
    while (rem >= T16 - bi) { rem -= T16 - bi; bi++; }
    int bj = bi + rem;
    if (bj * TBM >= k) return;   // inactive tile

    int tid = threadIdx.x, lane = tid & 31, warp = tid >> 5;
    int wm = warp & 1;   // 0..1 : 64-row strip
    int wn = warp >> 1;  // 0..1 : 64-col strip

    uint32_t sb  = (uint32_t)__cvta_generic_to_shared(smem);
    uint32_t mb0 = (uint32_t)__cvta_generic_to_shared(&s_mbar[0]);
    if (tid < STAGES) MBAR_INIT(mb0 + 8 * tid, 1);
    __syncthreads();

    const char* nfb = (const char*)g_nf2;
    int kb0 = split * NIT;   // first k-block of this split

    auto issue_stage = [&](int slot, int it_load) {
        // single thread: expect 32KB, two 16KB contiguous bulk copies
        uint32_t m = mb0 + 8 * slot;
        size_t kbOff = (size_t)(kb0 + it_load) * ((size_t)NROWS * 128);
        const char* srcA = nfb + kbOff + (size_t)(bi * TBM) * 128;
        const char* srcB = nfb + kbOff + (size_t)(bj * TBM) * 128;
        MBAR_ARRIVE_EXPECT(m, STAGE_BYTES);
        BULK_G2S(sb + slot * STAGE_BYTES,           srcA, OPBYTES, m);
        BULK_G2S(sb + slot * STAGE_BYTES + OPBYTES, srcB, OPBYTES, m);
    };

    // 64x64 accumulator per warp: acc[mt 0..3][nt16 0..3 x h 0..1][4]
    float acc[4][8][4];
#pragma unroll
    for (int mt = 0; mt < 4; mt++)
#pragma unroll
        for (int n = 0; n < 8; n++)
#pragma unroll
            for (int e = 0; e < 4; e++) acc[mt][n][e] = 0.0f;

    // prologue: stages 0,1 in flight
    if (tid == 0) { issue_stage(0, 0); issue_stage(1, 1); }

    // fixed per-warp fragment addressing (SW128 swizzle pre-baked in gmem)
    int raBase = wm * 64 + (lane & 15);                 // A rows; mt adds +16
    int gaSel  = lane >> 4;                             // A k-half within k16
    int rbBase = wn * 64 + (lane & 7) + ((lane >> 4) << 3);  // B rows; nt adds +16
    int gbSel  = (lane >> 3) & 1;                       // B k-half within k16

    int slot = 0;
    for (int it = 0; it < NIT; it++) {
        if (it > 0) __syncthreads();   // all warps done reading slot being refilled
        if (tid == 0 && it + 2 < NIT) {
            int js = slot + 2; if (js >= STAGES) js -= STAGES;
            issue_stage(js, it + 2);
        }
        MBAR_WAIT(mb0 + 8 * slot, (it / STAGES) & 1);

        uint32_t aB = sb + slot * STAGE_BYTES;
        uint32_t bB = aB + OPBYTES;

#pragma unroll
        for (int kk = 0; kk < 4; kk++) {   // four k16 steps per BK=64
            uint32_t af[4][4];
            uint32_t bf[4][4];
#pragma unroll
            for (int mt = 0; mt < 4; mt++) {
                int r = raBase + mt * 16;
                int g = kk * 2 + gaSel;
                uint32_t addr = aB + (uint32_t)(r * 128 + ((g ^ (r & 7)) << 4));
                asm volatile("ldmatrix.sync.aligned.m8n8.x4.shared.b16 {%0,%1,%2,%3}, [%4];\n"
                             : "=r"(af[mt][0]), "=r"(af[mt][1]), "=r"(af[mt][2]), "=r"(af[mt][3])
                             : "r"(addr));
            }
#pragma unroll
            for (int nt = 0; nt < 4; nt++) {
                int r = rbBase + nt * 16;
                int g = kk * 2 + gbSel;
                uint32_t addr = bB + (uint32_t)(r * 128 + ((g ^ (r & 7)) << 4));
                asm volatile("ldmatrix.sync.aligned.m8n8.x4.shared.b16 {%0,%1,%2,%3}, [%4];\n"
                             : "=r"(bf[nt][0]), "=r"(bf[nt][1]), "=r"(bf[nt][2]), "=r"(bf[nt][3])
                             : "r"(addr));
            }
            // 32 independent MMAs per k16 step.
            // bf[nt][0..3] = (n-lo,k-lo),(n-lo,k-hi),(n-hi,k-lo),(n-hi,k-hi)
#pragma unroll
            for (int mt = 0; mt < 4; mt++)
#pragma unroll
                for (int nt = 0; nt < 4; nt++)
#pragma unroll
                    for (int h = 0; h < 2; h++) {
                        asm volatile(
                            "mma.sync.aligned.m16n8k16.row.col.f32.bf16.bf16.f32 "
                            "{%0,%1,%2,%3}, {%4,%5,%6,%7}, {%8,%9}, {%0,%1,%2,%3};\n"
                            : "+f"(acc[mt][nt * 2 + h][0]), "+f"(acc[mt][nt * 2 + h][1]),
                              "+f"(acc[mt][nt * 2 + h][2]), "+f"(acc[mt][nt * 2 + h][3])
                            : "r"(af[mt][0]), "r"(af[mt][1]), "r"(af[mt][2]), "r"(af[mt][3]),
                              "r"(bf[nt][h * 2]), "r"(bf[nt][h * 2 + 1]));
                    }
        }
        slot++; if (slot >= STAGES) slot = 0;
    }

    // write split-partial tile (plain float2 stores, no atomics)
    float* part = g_part[pair * SPLITS + split];
#pragma unroll
    for (int mt = 0; mt < 4; mt++)
#pragma unroll
        for (int nt = 0; nt < 4; nt++)
#pragma unroll
            for (int h = 0; h < 2; h++) {
                int r0 = wm * 64 + mt * 16 + (lane >> 2);
                int c  = wn * 64 + nt * 16 + h * 8 + ((lane & 3) << 1);
                float* a4 = acc[mt][nt * 2 + h];
                *(float2*)(part + r0 * TBM + c)       = make_float2(a4[0], a4[1]);
                *(float2*)(part + (r0 + 8) * TBM + c) = make_float2(a4[2], a4[3]);
            }

    __threadfence();   // publish partial tile
    if (tid == 0) s_prev = atomicAdd(&g_tile_cnt[pair], 1u);
    __syncthreads();

    if (s_prev == SPLITS - 1) {   // last split: combine, square, accumulate
        __threadfence();
        const float invD = 1.0f / (float)DDIM;
        const float* pbase = g_part[pair * SPLITS];
        float ss = 0.0f;
        for (int idx = tid; idx < TBM * TBM; idx += 128) {
            float v = 0.0f;
#pragma unroll
            for (int sp = 0; sp < SPLITS; sp++)
                v += pbase[sp * TBM * TBM + idx];
            int r = idx >> 7, c = idx & 127;
            int gi = bi * TBM + r, gj = bj * TBM + c;
            if (gi < gj) {   // pad rows/cols are exact zeros
                v *= invD;
                ss += v * v;
            }
        }
#pragma unroll
        for (int o = 16; o > 0; o >>= 1) ss += __shfl_xor_sync(0xffffffffu, ss, o);
        if (lane == 0) s_red[warp] = ss;
        __syncthreads();
        if (tid == 0) {
            float bs = s_red[0] + s_red[1] + s_red[2] + s_red[3];
            atomicAdd(&g_sumsq, bs);
            __threadfence();
            unsigned p = atomicAdd(&g_pairs_done, 1u);
            int T = (k + TBM - 1) / TBM;
            unsigned tot = (unsigned)(T * (T + 1) / 2);
            if (p == tot - 1) {   // last tile overall: write the loss
                float total = atomicAdd(&g_sumsq, 0.0f);
                long long np = (long long)k * (k - 1) / 2;
                out[0] = (np > 0) ? (total / (float)np) : 0.0f;
            }
        }
    }
}

extern "C" void kernel_launch(void* const* d_in, const int* in_sizes, int n_in,
                              void* d_out, int out_size) {
    const float* w    = (const float*)d_in[0];  // [2048,1024,3,3] fp32
    const float* mask = (const float*)d_in[1];  // [2048,1,1,1]   fp32
    float* out = (float*)d_out;

    static bool attr_set = false;
    if (!attr_set) {
        cudaFuncSetAttribute(gram_kernel,
                             cudaFuncAttributeMaxDynamicSharedMemorySize, DSMEM_BYTES);
        attr_set = true;
    }

    normalize_kernel<<<NROWS, 256>>>(w, mask, out);
    gram_kernel<<<NPAIR * SPLITS, 128, DSMEM_BYTES>>>(out);
}

// round 11
// speedup vs baseline: 1.0840x; 1.0840x over previous
#include <cuda_runtime.h>
#include <cuda_bf16.h>
#include <cstdint>

// Problem constants
#define NROWS 2048
#define DDIM  9216             // C*KH*KW
#define TBM   128              // gram tile M = N = 128
#define T16   (NROWS / TBM)    // 16 tiles per dim (max)
#define NPAIR (T16 * (T16 + 1) / 2)   // 136 tile-pairs
#define SPLITS 8
#define KCH   (DDIM / SPLITS)  // 1152 k-elems per split
#define BK    64               // k-elems per pipeline stage (one k-block)
#define NIT   (KCH / BK)       // 18 iterations
#define KB_TOT (DDIM / BK)     // 144 k-blocks
#define STAGES 3
#define OPBYTES (TBM * 128)                 // 16 KB per operand per stage
#define STAGE_BYTES (2 * OPBYTES)           // 32 KB
#define DSMEM_BYTES (STAGES * STAGE_BYTES)  // 96 KB

// Device scratch (no allocations allowed)
// g_nf2 layout: [kblock][row][64 bf16], SW128 swizzle baked per 128B row:
// 16B group g of row r lives at byte r*128 + ((g ^ (r & 7)) * 16).
__device__ __align__(16) __nv_bfloat16 g_nf2[(size_t)KB_TOT * NROWS * BK];
__device__ int      g_k;
__device__ float    g_sumsq;
__device__ unsigned g_tile_cnt[NPAIR];
__device__ unsigned g_pairs_done;
__device__ float    g_part[NPAIR * SPLITS][TBM * TBM];  // split-K partial tiles

// ---------------- mbarrier / bulk-copy helpers (base sm_90 PTX) ----------------
#define MBAR_INIT(addr, cnt) \
    asm volatile("mbarrier.init.shared.b64 [%0], %1;" :: "r"(addr), "r"(cnt) : "memory")

#define MBAR_ARRIVE_EXPECT(addr, bytes) \
    asm volatile("mbarrier.arrive.expect_tx.shared.b64 _, [%0], %1;" \
                 :: "r"(addr), "r"(bytes) : "memory")

#define MBAR_ARRIVE(addr) \
    asm volatile("mbarrier.arrive.release.cta.shared::cta.b64 _, [%0];" \
                 :: "r"(addr) : "memory")

#define MBAR_WAIT(addr, parity) do {                                              \
    asm volatile("{\n\t.reg .pred P1;\n\t"                                        \
        "WL%=:\n\t"                                                               \
        "mbarrier.try_wait.parity.acquire.cta.shared::cta.b64 P1, [%0], %1, 0x989680;\n\t" \
        "@P1 bra.uni WD%=;\n\t"                                                   \
        "bra.uni WL%=;\n\t"                                                       \
        "WD%=:\n\t}"                                                              \
        :: "r"(addr), "r"(parity) : "memory");                                    \
} while (0)

#define BULK_G2S(dst, src, bytes, mbar) \
    asm volatile("cp.async.bulk.shared::cta.global.mbarrier::complete_tx::bytes " \
                 "[%0], [%1], %2, [%3];" \
                 :: "r"(dst), "l"(src), "r"(bytes), "r"(mbar) : "memory")

// ---------------------------------------------------------------------------
// Kernel 1: per-row normalize + inline mask scan + pad-row zeroing.
// Writes g_nf2 in k-block-major, swizzle-baked layout.
// ---------------------------------------------------------------------------
__global__ void __launch_bounds__(256) normalize_kernel(const float* __restrict__ w,
                                                        const float* __restrict__ mask,
                                                        float* __restrict__ out) {
    __shared__ int s_cnt[32];
    __shared__ int s_posk[2];
    int row = blockIdx.x;
    int tid = threadIdx.x;
    int lane = tid & 31, wid = tid >> 5;
    const unsigned full = 0xffffffffu;

    // inline scan: each thread owns mask[8t .. 8t+7]
    const float4* m4 = (const float4*)mask;
    float4 ma = m4[2 * tid], mb = m4[2 * tid + 1];
    int c8 = (ma.x > 0.5f) + (ma.y > 0.5f) + (ma.z > 0.5f) + (ma.w > 0.5f)
           + (mb.x > 0.5f) + (mb.y > 0.5f) + (mb.z > 0.5f) + (mb.w > 0.5f);
    int incl = c8;
#pragma unroll
    for (int o = 1; o < 32; o <<= 1) {
        int v = __shfl_up_sync(full, incl, o);
        if (lane >= o) incl += v;
    }
    if (lane == 31) s_cnt[wid] = incl;
    __syncthreads();
    if (wid == 0) {
        int iv = (lane < 8) ? s_cnt[lane] : 0;
#pragma unroll
        for (int o = 1; o < 8; o <<= 1) {
            int u = __shfl_up_sync(full, iv, o);
            if (lane >= o) iv += u;
        }
        if (lane < 8) s_cnt[lane] = iv;
    }
    __syncthreads();
    if (tid == (row >> 3)) {
        int exclWarp = (wid > 0) ? s_cnt[wid - 1] : 0;
        int excl8 = exclWarp + incl - c8;
        int base = row & ~7;
        int p = excl8;
        bool act = false;
#pragma unroll
        for (int q = 0; q < 8; q++) {
            int rr = base + q;
            bool a = mask[rr] > 0.5f;
            if (rr < row) p += a;
            else if (rr == row) act = a;
        }
        s_posk[0] = act ? p : -(row - p) - 1;   // inactive: encode inactive index
        s_posk[1] = s_cnt[7];
    }
    __syncthreads();
    int pos = s_posk[0];
    int k   = s_posk[1];

    if (row == 0 && tid < NPAIR) g_tile_cnt[tid] = 0u;
    if (row == 0 && tid == 0) {
        g_k = k; g_sumsq = 0.0f; g_pairs_done = 0u;
        if (k < 2) out[0] = 0.0f;
    }

    uint2* nf2 = (uint2*)g_nf2;   // 8B units; per kb block = NROWS*16 uint2

    if (pos < 0) {
        // zero pad rows [k, ceil(k/128)*128) so gram tiles see exact zeros
        int padIdx = -pos - 1;
        int T = (k + TBM - 1) >> 7;
        int padRows = T * TBM - k;
        if (padIdx < padRows) {
            int prow = k + padIdx;
            uint2 z = make_uint2(0u, 0u);
#pragma unroll
            for (int i = 0; i < 9; i++) {
                int c = tid + i * 256;            // 8B chunk index 0..2303
                int kb = c >> 4, rem = c & 15;
                int g16 = rem >> 1, half = rem & 1;
                size_t idx = (size_t)kb * (NROWS * 16) + (size_t)prow * 16
                           + ((g16 ^ (prow & 7)) << 1) + half;
                nf2[idx] = z;
            }
        }
        return;
    }

    const float4* src = (const float4*)(w + (size_t)row * DDIM);
    float4 v[9];
    float sum = 0.0f, sumsq = 0.0f;
#pragma unroll
    for (int i = 0; i < 9; i++) {
        v[i] = src[tid + i * 256];
        sum   += v[i].x + v[i].y + v[i].z + v[i].w;
        sumsq += v[i].x * v[i].x + v[i].y * v[i].y + v[i].z * v[i].z + v[i].w * v[i].w;
    }

    __shared__ float rs[256], rq[256];
    rs[tid] = sum; rq[tid] = sumsq;
    __syncthreads();
    for (int o = 128; o > 0; o >>= 1) {
        if (tid < o) { rs[tid] += rs[tid + o]; rq[tid] += rq[tid + o]; }
        __syncthreads();
    }
    __shared__ float s_mean, s_inv;
    if (tid == 0) {
        float mean = rs[0] * (1.0f / DDIM);
        float var  = fmaxf(rq[0] * (1.0f / DDIM) - mean * mean, 0.0f);
        float stdv = sqrtf(var);
        s_mean = mean;
        s_inv  = (stdv == 0.0f) ? 1.0f : (1.0f / stdv);
    }
    __syncthreads();
    float mean = s_mean, inv = s_inv;

#pragma unroll
    for (int i = 0; i < 9; i++) {
        __nv_bfloat162 lo = __floats2bfloat162_rn((v[i].x - mean) * inv, (v[i].y - mean) * inv);
        __nv_bfloat162 hi = __floats2bfloat162_rn((v[i].z - mean) * inv, (v[i].w - mean) * inv);
        uint2 o;
        o.x = *(uint32_t*)&lo;
        o.y = *(uint32_t*)&hi;
        int c = tid + i * 256;                // 8B chunk index (4 bf16)
        int kb = c >> 4, rem = c & 15;
        int g16 = rem >> 1, half = rem & 1;
        size_t idx = (size_t)kb * (NROWS * 16) + (size_t)pos * 16
                   + ((g16 ^ (pos & 7)) << 1) + half;
        nf2[idx] = o;
    }
}

// ---------------------------------------------------------------------------
// Kernel 2: 128x128 bf16 Gram via mma.sync, split-K=8, 8 warps (32x64 tiles),
// full/empty mbarrier pipeline (NO per-iteration __syncthreads — warps run
// decoupled). Stage fed by two 16KB cp.async.bulk copies from one thread.
// Last split combines partials + squares + finalizes.
// ---------------------------------------------------------------------------
__global__ void __launch_bounds__(256, 2) gram_kernel(float* __restrict__ out) {
    extern __shared__ __align__(16) char smem[];
    __shared__ __align__(8) unsigned long long s_mbar[2 * STAGES];  // [full | empty]
    __shared__ float s_red[8];
    __shared__ unsigned s_prev;

    int k = g_k;
    int blk = blockIdx.x;
    int pair = blk >> 3;
    int split = blk & 7;
    int bi = 0, rem = pair;
    while (rem >= T16 - bi) { rem -= T16 - bi; bi++; }
    int bj = bi + rem;
    if (bj * TBM >= k) return;   // inactive tile

    int tid = threadIdx.x, lane = tid & 31, warp = tid >> 5;
    int wm = warp & 3;   // 0..3 : 32-row strip
    int wn = warp >> 2;  // 0..1 : 64-col strip

    uint32_t sb  = (uint32_t)__cvta_generic_to_shared(smem);
    uint32_t mb0 = (uint32_t)__cvta_generic_to_shared(&s_mbar[0]);
    uint32_t me0 = mb0 + 8 * STAGES;
    if (tid < STAGES)      MBAR_INIT(mb0 + 8 * tid, 1);            // full: tx-based
    else if (tid < 2 * STAGES) MBAR_INIT(me0 + 8 * (tid - STAGES), 8);  // empty: 8 warps
    __syncthreads();   // barriers visible before any use

    const char* nfb = (const char*)g_nf2;
    int kb0 = split * NIT;   // first k-block of this split

    auto issue_stage = [&](int slot, int it_load) {
        // single thread: expect 32KB, two 16KB contiguous bulk copies
        uint32_t m = mb0 + 8 * slot;
        size_t kbOff = (size_t)(kb0 + it_load) * ((size_t)NROWS * 128);
        const char* srcA = nfb + kbOff + (size_t)(bi * TBM) * 128;
        const char* srcB = nfb + kbOff + (size_t)(bj * TBM) * 128;
        MBAR_ARRIVE_EXPECT(m, STAGE_BYTES);
        BULK_G2S(sb + slot * STAGE_BYTES,           srcA, OPBYTES, m);
        BULK_G2S(sb + slot * STAGE_BYTES + OPBYTES, srcB, OPBYTES, m);
    };

    float acc[2][8][4];
#pragma unroll
    for (int mt = 0; mt < 2; mt++)
#pragma unroll
        for (int n = 0; n < 8; n++)
#pragma unroll
            for (int e = 0; e < 4; e++) acc[mt][n][e] = 0.0f;

    // prologue: stages 0,1 in flight (round 0 -> no empty wait needed)
    if (tid == 0) { issue_stage(0, 0); issue_stage(1, 1); }

    // fixed per-warp fragment addressing (SW128 swizzle pre-baked in gmem)
    int raBase = wm * 32 + (lane & 15);                 // A rows; mt adds +16
    int gaSel  = lane >> 4;                             // A k-half within k16
    int rbBase = wn * 64 + (lane & 7) + ((lane >> 4) << 3);  // B rows; nt adds +16
    int gbSel  = (lane >> 3) & 1;                       // B k-half within k16

    int slot = 0;
    for (int it = 0; it < NIT; it++) {
        // producer: refill slot (it+2)%STAGES once all warps released it
        if (tid == 0 && it + 2 < NIT) {
            int jl = it + 2;
            int js = jl % STAGES;
            int jr = jl / STAGES;
            if (jr >= 1) MBAR_WAIT(me0 + 8 * js, (jr - 1) & 1);  // slot drained
            issue_stage(js, jl);
        }
        MBAR_WAIT(mb0 + 8 * slot, (it / STAGES) & 1);   // data arrived

        uint32_t aB = sb + slot * STAGE_BYTES;
        uint32_t bB = aB + OPBYTES;

#pragma unroll
        for (int kk = 0; kk < 4; kk++) {   // four k16 steps per BK=64
            uint32_t af[2][4];
            uint32_t bf[4][4];
#pragma unroll
            for (int mt = 0; mt < 2; mt++) {
                int r = raBase + mt * 16;
                int g = kk * 2 + gaSel;
                uint32_t addr = aB + (uint32_t)(r * 128 + ((g ^ (r & 7)) << 4));
                asm volatile("ldmatrix.sync.aligned.m8n8.x4.shared.b16 {%0,%1,%2,%3}, [%4];\n"
                             : "=r"(af[mt][0]), "=r"(af[mt][1]), "=r"(af[mt][2]), "=r"(af[mt][3])
                             : "r"(addr));
            }
#pragma unroll
            for (int nt = 0; nt < 4; nt++) {
                int r = rbBase + nt * 16;
                int g = kk * 2 + gbSel;
                uint32_t addr = bB + (uint32_t)(r * 128 + ((g ^ (r & 7)) << 4));
                asm volatile("ldmatrix.sync.aligned.m8n8.x4.shared.b16 {%0,%1,%2,%3}, [%4];\n"
                             : "=r"(bf[nt][0]), "=r"(bf[nt][1]), "=r"(bf[nt][2]), "=r"(bf[nt][3])
                             : "r"(addr));
            }
            // bf[nt][0..3] = (n-lo,k-lo),(n-lo,k-hi),(n-hi,k-lo),(n-hi,k-hi)
#pragma unroll
            for (int mt = 0; mt < 2; mt++)
#pragma unroll
                for (int nt = 0; nt < 4; nt++)
#pragma unroll
                    for (int h = 0; h < 2; h++) {
                        asm volatile(
                            "mma.sync.aligned.m16n8k16.row.col.f32.bf16.bf16.f32 "
                            "{%0,%1,%2,%3}, {%4,%5,%6,%7}, {%8,%9}, {%0,%1,%2,%3};\n"
                            : "+f"(acc[mt][nt * 2 + h][0]), "+f"(acc[mt][nt * 2 + h][1]),
                              "+f"(acc[mt][nt * 2 + h][2]), "+f"(acc[mt][nt * 2 + h][3])
                            : "r"(af[mt][0]), "r"(af[mt][1]), "r"(af[mt][2]), "r"(af[mt][3]),
                              "r"(bf[nt][h * 2]), "r"(bf[nt][h * 2 + 1]));
                    }
        }
        // this warp is done reading `slot` (ldmatrix results in registers)
        if (lane == 0) MBAR_ARRIVE(me0 + 8 * slot);
        slot++; if (slot >= STAGES) slot = 0;
    }

    // write split-partial tile (plain float2 stores, no atomics)
    float* part = g_part[pair * SPLITS + split];
#pragma unroll
    for (int mt = 0; mt < 2; mt++)
#pragma unroll
        for (int nt = 0; nt < 4; nt++)
#pragma unroll
            for (int h = 0; h < 2; h++) {
                int r0 = wm * 32 + mt * 16 + (lane >> 2);
                int c  = wn * 64 + nt * 16 + h * 8 + ((lane & 3) << 1);
                float* a4 = acc[mt][nt * 2 + h];
                *(float2*)(part + r0 * TBM + c)       = make_float2(a4[0], a4[1]);
                *(float2*)(part + (r0 + 8) * TBM + c) = make_float2(a4[2], a4[3]);
            }

    __threadfence();   // publish partial tile
    __syncthreads();
    if (tid == 0) s_prev = atomicAdd(&g_tile_cnt[pair], 1u);
    __syncthreads();

    if (s_prev == SPLITS - 1) {   // last split: combine, square, accumulate
        __threadfence();
        const float invD = 1.0f / (float)DDIM;
        const float* pbase = g_part[pair * SPLITS];
        float ss = 0.0f;
        for (int idx = tid; idx < TBM * TBM; idx += 256) {
            float v = 0.0f;
#pragma unroll
            for (int sp = 0; sp < SPLITS; sp++)
                v += pbase[sp * TBM * TBM + idx];
            int r = idx >> 7, c = idx & 127;
            int gi = bi * TBM + r, gj = bj * TBM + c;
            if (gi < gj) {   // pad rows/cols are exact zeros
                v *= invD;
                ss += v * v;
            }
        }
#pragma unroll
        for (int o = 16; o > 0; o >>= 1) ss += __shfl_xor_sync(0xffffffffu, ss, o);
        if (lane == 0) s_red[warp] = ss;
        __syncthreads();
        if (tid == 0) {
            float bs = 0.0f;
#pragma unroll
            for (int w2 = 0; w2 < 8; w2++) bs += s_red[w2];
            atomicAdd(&g_sumsq, bs);
            __threadfence();
            unsigned p = atomicAdd(&g_pairs_done, 1u);
            int T = (k + TBM - 1) / TBM;
            unsigned tot = (unsigned)(T * (T + 1) / 2);
            if (p == tot - 1) {   // last tile overall: write the loss
                float total = atomicAdd(&g_sumsq, 0.0f);
                long long np = (long long)k * (k - 1) / 2;
                out[0] = (np > 0) ? (total / (float)np) : 0.0f;
            }
        }
    }
}

extern "C" void kernel_launch(void* const* d_in, const int* in_sizes, int n_in,
                              void* d_out, int out_size) {
    const float* w    = (const float*)d_in[0];  // [2048,1024,3,3] fp32
    const float* mask = (const float*)d_in[1];  // [2048,1,1,1]   fp32
    float* out = (float*)d_out;

    static bool attr_set = false;
    if (!attr_set) {
        cudaFuncSetAttribute(gram_kernel,
                             cudaFuncAttributeMaxDynamicSharedMemorySize, DSMEM_BYTES);
        attr_set = true;
    }

    normalize_kernel<<<NROWS, 256>>>(w, mask, out);
    gram_kernel<<<NPAIR * SPLITS, 256, DSMEM_BYTES>>>(out);
}

// round 12
// speedup vs baseline: 1.1637x; 1.0735x over previous
#include <cuda_runtime.h>
#include <cuda_bf16.h>
#include <cstdint>

// Problem constants
#define NROWS 2048
#define DDIM  9216             // C*KH*KW
#define TBM   128              // gram tile M = N = 128
#define T16   (NROWS / TBM)    // 16 tiles per dim (max)
#define NPAIR (T16 * (T16 + 1) / 2)   // 136 tile-pairs
#define SPLITS 4
#define KCH   (DDIM / SPLITS)  // 2304 k-elems per split
#define BK    64               // k-elems per pipeline stage (one k-block)
#define NIT   (KCH / BK)       // 36 iterations
#define KB_TOT (DDIM / BK)     // 144 k-blocks
#define STAGES 4
#define OPBYTES (TBM * 128)                 // 16 KB per operand per stage
#define STAGE_BYTES (2 * OPBYTES)           // 32 KB
#define DSMEM_BYTES (STAGES * STAGE_BYTES)  // 128 KB

// Device scratch (no allocations allowed)
// g_nf2 layout: [kblock][row][64 bf16], SW128 swizzle baked per 128B row:
// 16B group g of row r lives at byte r*128 + ((g ^ (r & 7)) * 16).
__device__ __align__(16) __nv_bfloat16 g_nf2[(size_t)KB_TOT * NROWS * BK];
__device__ int      g_k;
__device__ float    g_sumsq;
__device__ unsigned g_tile_cnt[NPAIR];
__device__ unsigned g_pairs_done;
__device__ float    g_part[NPAIR * SPLITS][TBM * TBM];  // split-K partial tiles

// ---------------- mbarrier / bulk-copy helpers (base sm_90 PTX) ----------------
#define MBAR_INIT(addr, cnt) \
    asm volatile("mbarrier.init.shared.b64 [%0], %1;" :: "r"(addr), "r"(cnt) : "memory")

#define MBAR_ARRIVE_EXPECT(addr, bytes) \
    asm volatile("mbarrier.arrive.expect_tx.shared.b64 _, [%0], %1;" \
                 :: "r"(addr), "r"(bytes) : "memory")

#define MBAR_ARRIVE(addr) \
    asm volatile("mbarrier.arrive.release.cta.shared::cta.b64 _, [%0];" \
                 :: "r"(addr) : "memory")

#define MBAR_WAIT(addr, parity) do {                                              \
    asm volatile("{\n\t.reg .pred P1;\n\t"                                        \
        "WL%=:\n\t"                                                               \
        "mbarrier.try_wait.parity.acquire.cta.shared::cta.b64 P1, [%0], %1, 0x989680;\n\t" \
        "@P1 bra.uni WD%=;\n\t"                                                   \
        "bra.uni WL%=;\n\t"                                                       \
        "WD%=:\n\t}"                                                              \
        :: "r"(addr), "r"(parity) : "memory");                                    \
} while (0)

#define BULK_G2S(dst, src, bytes, mbar) \
    asm volatile("cp.async.bulk.shared::cta.global.mbarrier::complete_tx::bytes " \
                 "[%0], [%1], %2, [%3];" \
                 :: "r"(dst), "l"(src), "r"(bytes), "r"(mbar) : "memory")

// ---------------------------------------------------------------------------
// Kernel 1: per-row normalize + inline mask scan + pad-row zeroing.
// Writes g_nf2 in k-block-major, swizzle-baked layout.
// ---------------------------------------------------------------------------
__global__ void __launch_bounds__(256) normalize_kernel(const float* __restrict__ w,
                                                        const float* __restrict__ mask,
                                                        float* __restrict__ out) {
    __shared__ int s_cnt[32];
    __shared__ int s_posk[2];
    int row = blockIdx.x;
    int tid = threadIdx.x;
    int lane = tid & 31, wid = tid >> 5;
    const unsigned full = 0xffffffffu;

    // inline scan: each thread owns mask[8t .. 8t+7]
    const float4* m4 = (const float4*)mask;
    float4 ma = m4[2 * tid], mb = m4[2 * tid + 1];
    int c8 = (ma.x > 0.5f) + (ma.y > 0.5f) + (ma.z > 0.5f) + (ma.w > 0.5f)
           + (mb.x > 0.5f) + (mb.y > 0.5f) + (mb.z > 0.5f) + (mb.w > 0.5f);
    int incl = c8;
#pragma unroll
    for (int o = 1; o < 32; o <<= 1) {
        int v = __shfl_up_sync(full, incl, o);
        if (lane >= o) incl += v;
    }
    if (lane == 31) s_cnt[wid] = incl;
    __syncthreads();
    if (wid == 0) {
        int iv = (lane < 8) ? s_cnt[lane] : 0;
#pragma unroll
        for (int o = 1; o < 8; o <<= 1) {
            int u = __shfl_up_sync(full, iv, o);
            if (lane >= o) iv += u;
        }
        if (lane < 8) s_cnt[lane] = iv;
    }
    __syncthreads();
    if (tid == (row >> 3)) {
        int exclWarp = (wid > 0) ? s_cnt[wid - 1] : 0;
        int excl8 = exclWarp + incl - c8;
        int base = row & ~7;
        int p = excl8;
        bool act = false;
#pragma unroll
        for (int q = 0; q < 8; q++) {
            int rr = base + q;
            bool a = mask[rr] > 0.5f;
            if (rr < row) p += a;
            else if (rr == row) act = a;
        }
        s_posk[0] = act ? p : -(row - p) - 1;   // inactive: encode inactive index
        s_posk[1] = s_cnt[7];
    }
    __syncthreads();
    int pos = s_posk[0];
    int k   = s_posk[1];

    if (row == 0 && tid < NPAIR) g_tile_cnt[tid] = 0u;
    if (row == 0 && tid == 0) {
        g_k = k; g_sumsq = 0.0f; g_pairs_done = 0u;
        if (k < 2) out[0] = 0.0f;
    }

    uint2* nf2 = (uint2*)g_nf2;   // 8B units; per kb block = NROWS*16 uint2

    if (pos < 0) {
        // zero pad rows [k, ceil(k/128)*128) so gram tiles see exact zeros
        int padIdx = -pos - 1;
        int T = (k + TBM - 1) >> 7;
        int padRows = T * TBM - k;
        if (padIdx < padRows) {
            int prow = k + padIdx;
            uint2 z = make_uint2(0u, 0u);
#pragma unroll
            for (int i = 0; i < 9; i++) {
                int c = tid + i * 256;            // 8B chunk index 0..2303
                int kb = c >> 4, rem = c & 15;
                int g16 = rem >> 1, half = rem & 1;
                size_t idx = (size_t)kb * (NROWS * 16) + (size_t)prow * 16
                           + ((g16 ^ (prow & 7)) << 1) + half;
                nf2[idx] = z;
            }
        }
        return;
    }

    const float4* src = (const float4*)(w + (size_t)row * DDIM);
    float4 v[9];
    float sum = 0.0f, sumsq = 0.0f;
#pragma unroll
    for (int i = 0; i < 9; i++) {
        v[i] = src[tid + i * 256];
        sum   += v[i].x + v[i].y + v[i].z + v[i].w;
        sumsq += v[i].x * v[i].x + v[i].y * v[i].y + v[i].z * v[i].z + v[i].w * v[i].w;
    }

    __shared__ float rs[256], rq[256];
    rs[tid] = sum; rq[tid] = sumsq;
    __syncthreads();
    for (int o = 128; o > 0; o >>= 1) {
        if (tid < o) { rs[tid] += rs[tid + o]; rq[tid] += rq[tid + o]; }
        __syncthreads();
    }
    __shared__ float s_mean, s_inv;
    if (tid == 0) {
        float mean = rs[0] * (1.0f / DDIM);
        float var  = fmaxf(rq[0] * (1.0f / DDIM) - mean * mean, 0.0f);
        float stdv = sqrtf(var);
        s_mean = mean;
        s_inv  = (stdv == 0.0f) ? 1.0f : (1.0f / stdv);
    }
    __syncthreads();
    float mean = s_mean, inv = s_inv;

#pragma unroll
    for (int i = 0; i < 9; i++) {
        __nv_bfloat162 lo = __floats2bfloat162_rn((v[i].x - mean) * inv, (v[i].y - mean) * inv);
        __nv_bfloat162 hi = __floats2bfloat162_rn((v[i].z - mean) * inv, (v[i].w - mean) * inv);
        uint2 o;
        o.x = *(uint32_t*)&lo;
        o.y = *(uint32_t*)&hi;
        int c = tid + i * 256;                // 8B chunk index (4 bf16)
        int kb = c >> 4, rem = c & 15;
        int g16 = rem >> 1, half = rem & 1;
        size_t idx = (size_t)kb * (NROWS * 16) + (size_t)pos * 16
                   + ((g16 ^ (pos & 7)) << 1) + half;
        nf2[idx] = o;
    }
}

// ---------------------------------------------------------------------------
// Kernel 2: 128x128 bf16 Gram via mma.sync, split-K=4, 8 warps (32x64 tiles),
// 1 CTA/SM (high regs), EXPLICIT fragment double-buffer (LDSM for step kk+1
// overlaps MMAs of step kk), full/empty mbarrier pipeline, 4-stage bulk ring.
// Last split combines partials + squares + finalizes.
// ---------------------------------------------------------------------------
__global__ void __launch_bounds__(256, 1) gram_kernel(float* __restrict__ out) {
    extern __shared__ __align__(16) char smem[];
    __shared__ __align__(8) unsigned long long s_mbar[2 * STAGES];  // [full | empty]
    __shared__ float s_red[8];
    __shared__ unsigned s_prev;

    int k = g_k;
    int blk = blockIdx.x;
    int pair = blk >> 2;
    int split = blk & 3;
    int bi = 0, rem = pair;
    while (rem >= T16 - bi) { rem -= T16 - bi; bi++; }
    int bj = bi + rem;
    if (bj * TBM >= k) return;   // inactive tile

    int tid = threadIdx.x, lane = tid & 31, warp = tid >> 5;
    int wm = warp & 3;   // 0..3 : 32-row strip
    int wn = warp >> 2;  // 0..1 : 64-col strip

    uint32_t sb  = (uint32_t)__cvta_generic_to_shared(smem);
    uint32_t mb0 = (uint32_t)__cvta_generic_to_shared(&s_mbar[0]);
    uint32_t me0 = mb0 + 8 * STAGES;
    if (tid < STAGES)          MBAR_INIT(mb0 + 8 * tid, 1);             // full: tx
    else if (tid < 2 * STAGES) MBAR_INIT(me0 + 8 * (tid - STAGES), 8);  // empty: 8 warps
    __syncthreads();   // barriers visible before any use

    const char* nfb = (const char*)g_nf2;
    int kb0 = split * NIT;   // first k-block of this split

    auto issue_stage = [&](int slot_, int it_load) {
        uint32_t m = mb0 + 8 * slot_;
        size_t kbOff = (size_t)(kb0 + it_load) * ((size_t)NROWS * 128);
        const char* srcA = nfb + kbOff + (size_t)(bi * TBM) * 128;
        const char* srcB = nfb + kbOff + (size_t)(bj * TBM) * 128;
        MBAR_ARRIVE_EXPECT(m, STAGE_BYTES);
        BULK_G2S(sb + slot_ * STAGE_BYTES,           srcA, OPBYTES, m);
        BULK_G2S(sb + slot_ * STAGE_BYTES + OPBYTES, srcB, OPBYTES, m);
    };

    float acc[2][8][4];
#pragma unroll
    for (int mt = 0; mt < 2; mt++)
#pragma unroll
        for (int n = 0; n < 8; n++)
#pragma unroll
            for (int e = 0; e < 4; e++) acc[mt][n][e] = 0.0f;

    // prologue: STAGES-1 stages in flight
    if (tid == 0) {
#pragma unroll
        for (int s = 0; s < STAGES - 1; s++) issue_stage(s, s);
    }

    // fixed per-warp fragment addressing (SW128 swizzle pre-baked in gmem)
    int raBase = wm * 32 + (lane & 15);                 // A rows; mt adds +16
    int gaSel  = lane >> 4;                             // A k-half within k16
    int rbBase = wn * 64 + (lane & 7) + ((lane >> 4) << 3);  // B rows; nt adds +16
    int gbSel  = (lane >> 3) & 1;                       // B k-half within k16

    // double-buffered fragments
    uint32_t af[2][2][4];
    uint32_t bf[2][4][4];

#define LD_FRAGS(buf, aB_, bB_, kk_) do {                                         \
    _Pragma("unroll")                                                             \
    for (int mt = 0; mt < 2; mt++) {                                              \
        int r = raBase + mt * 16;                                                 \
        int g = (kk_) * 2 + gaSel;                                                \
        uint32_t addr = (aB_) + (uint32_t)(r * 128 + ((g ^ (r & 7)) << 4));       \
        asm volatile("ldmatrix.sync.aligned.m8n8.x4.shared.b16 {%0,%1,%2,%3}, [%4];\n" \
                     : "=r"(af[buf][mt][0]), "=r"(af[buf][mt][1]),                \
                       "=r"(af[buf][mt][2]), "=r"(af[buf][mt][3])                 \
                     : "r"(addr));                                                \
    }                                                                             \
    _Pragma("unroll")                                                             \
    for (int nt = 0; nt < 4; nt++) {                                              \
        int r = rbBase + nt * 16;                                                 \
        int g = (kk_) * 2 + gbSel;                                                \
        uint32_t addr = (bB_) + (uint32_t)(r * 128 + ((g ^ (r & 7)) << 4));       \
        asm volatile("ldmatrix.sync.aligned.m8n8.x4.shared.b16 {%0,%1,%2,%3}, [%4];\n" \
                     : "=r"(bf[buf][nt][0]), "=r"(bf[buf][nt][1]),                \
                       "=r"(bf[buf][nt][2]), "=r"(bf[buf][nt][3])                 \
                     : "r"(addr));                                                \
    }                                                                             \
} while (0)

    // initial: wait stage 0, preload frags for (it=0, kk=0) into buf 0
    MBAR_WAIT(mb0 + 0, 0);
    LD_FRAGS(0, sb, sb + OPBYTES, 0);

    int slot = 0;
    for (int it = 0; it < NIT; it++) {
        // producer: refill slot (it+3)%4 once all warps released it
        if (tid == 0 && it + STAGES - 1 < NIT) {
            int jl = it + STAGES - 1;
            int js = jl & (STAGES - 1);
            int jr = jl >> 2;
            if (jr >= 1) MBAR_WAIT(me0 + 8 * js, (jr - 1) & 1);  // slot drained
            issue_stage(js, jl);
        }

        uint32_t aB = sb + slot * STAGE_BYTES, bB = aB + OPBYTES;
        int nslot = (slot + 1) & (STAGES - 1);
        uint32_t aBn = sb + nslot * STAGE_BYTES, bBn = aBn + OPBYTES;

#pragma unroll
        for (int kk = 0; kk < 4; kk++) {   // four k16 steps per BK=64
            const int cb = kk & 1, nb = cb ^ 1;
            // prefetch fragments for the NEXT k16 step (overlaps MMAs below)
            if (kk < 3) {
                LD_FRAGS(nb, aB, bB, kk + 1);
            } else if (it + 1 < NIT) {
                MBAR_WAIT(mb0 + 8 * nslot, ((it + 1) >> 2) & 1);  // next stage data
                LD_FRAGS(nb, aBn, bBn, 0);
            }
            // 16 independent MMAs on buffer cb
            // bf[cb][nt][0..3] = (n-lo,k-lo),(n-lo,k-hi),(n-hi,k-lo),(n-hi,k-hi)
#pragma unroll
            for (int mt = 0; mt < 2; mt++)
#pragma unroll
                for (int nt = 0; nt < 4; nt++)
#pragma unroll
                    for (int h = 0; h < 2; h++) {
                        asm volatile(
                            "mma.sync.aligned.m16n8k16.row.col.f32.bf16.bf16.f32 "
                            "{%0,%1,%2,%3}, {%4,%5,%6,%7}, {%8,%9}, {%0,%1,%2,%3};\n"
                            : "+f"(acc[mt][nt * 2 + h][0]), "+f"(acc[mt][nt * 2 + h][1]),
                              "+f"(acc[mt][nt * 2 + h][2]), "+f"(acc[mt][nt * 2 + h][3])
                            : "r"(af[cb][mt][0]), "r"(af[cb][mt][1]),
                              "r"(af[cb][mt][2]), "r"(af[cb][mt][3]),
                              "r"(bf[cb][nt][h * 2]), "r"(bf[cb][nt][h * 2 + 1]));
                    }
        }
        // this warp is done reading `slot` (all its LDSM results consumed)
        if (lane == 0) MBAR_ARRIVE(me0 + 8 * slot);
        slot = nslot;
    }
#undef LD_FRAGS

    // write split-partial tile (plain float2 stores, no atomics)
    float* part = g_part[pair * SPLITS + split];
#pragma unroll
    for (int mt = 0; mt < 2; mt++)
#pragma unroll
        for (int nt = 0; nt < 4; nt++)
#pragma unroll
            for (int h = 0; h < 2; h++) {
                int r0 = wm * 32 + mt * 16 + (lane >> 2);
                int c  = wn * 64 + nt * 16 + h * 8 + ((lane & 3) << 1);
                float* a4 = acc[mt][nt * 2 + h];
                *(float2*)(part + r0 * TBM + c)       = make_float2(a4[0], a4[1]);
                *(float2*)(part + (r0 + 8) * TBM + c) = make_float2(a4[2], a4[3]);
            }

    __threadfence();   // publish partial tile
    __syncthreads();
    if (tid == 0) s_prev = atomicAdd(&g_tile_cnt[pair], 1u);
    __syncthreads();

    if (s_prev == SPLITS - 1) {   // last split: combine, square, accumulate
        __threadfence();
        const float invD = 1.0f / (float)DDIM;
        const float* pbase = g_part[pair * SPLITS];
        float ss = 0.0f;
        for (int idx = tid; idx < TBM * TBM; idx += 256) {
            float v = 0.0f;
#pragma unroll
            for (int sp = 0; sp < SPLITS; sp++)
                v += pbase[sp * TBM * TBM + idx];
            int r = idx >> 7, c = idx & 127;
            int gi = bi * TBM + r, gj = bj * TBM + c;
            if (gi < gj) {   // pad rows/cols are exact zeros
                v *= invD;
                ss += v * v;
            }
        }
#pragma unroll
        for (int o = 16; o > 0; o >>= 1) ss += __shfl_xor_sync(0xffffffffu, ss, o);
        if (lane == 0) s_red[warp] = ss;
        __syncthreads();
        if (tid == 0) {
            float bs = 0.0f;
#pragma unroll
            for (int w2 = 0; w2 < 8; w2++) bs += s_red[w2];
            atomicAdd(&g_sumsq, bs);
            __threadfence();
            unsigned p = atomicAdd(&g_pairs_done, 1u);
            int T = (k + TBM - 1) / TBM;
            unsigned tot = (unsigned)(T * (T + 1) / 2);
            if (p == tot - 1) {   // last tile overall: write the loss
                float total = atomicAdd(&g_sumsq, 0.0f);
                long long np = (long long)k * (k - 1) / 2;
                out[0] = (np > 0) ? (total / (float)np) : 0.0f;
            }
        }
    }
}

extern "C" void kernel_launch(void* const* d_in, const int* in_sizes, int n_in,
                              void* d_out, int out_size) {
    const float* w    = (const float*)d_in[0];  // [2048,1024,3,3] fp32
    const float* mask = (const float*)d_in[1];  // [2048,1,1,1]   fp32
    float* out = (float*)d_out;

    static bool attr_set = false;
    if (!attr_set) {
        cudaFuncSetAttribute(gram_kernel,
                             cudaFuncAttributeMaxDynamicSharedMemorySize, DSMEM_BYTES);
        attr_set = true;
    }

    normalize_kernel<<<NROWS, 256>>>(w, mask, out);
    gram_kernel<<<NPAIR * SPLITS, 256, DSMEM_BYTES>>>(out);
}

// round 13
// speedup vs baseline: 1.2137x; 1.0430x over previous
#include <cuda_runtime.h>
#include <cuda_bf16.h>
#include <cstdint>

// Problem constants
#define NROWS 2048
#define DDIM  9216             // C*KH*KW
#define TBM   128              // gram tile M = N = 128
#define T16   (NROWS / TBM)    // 16 tiles per dim (max)
#define NPAIR (T16 * (T16 + 1) / 2)   // 136 tile-pairs
#define SPLITS 4
#define KCH   (DDIM / SPLITS)  // 2304 k-elems per split
#define BK    64               // k-elems per pipeline stage (one k-block)
#define NIT   (KCH / BK)       // 36 iterations
#define KB_TOT (DDIM / BK)     // 144 k-blocks
#define STAGES 4
#define OPBYTES (TBM * 128)                 // 16 KB per operand per stage
#define STAGE_BYTES (2 * OPBYTES)           // 32 KB
#define DSMEM_BYTES (STAGES * STAGE_BYTES)  // 128 KB
#define NTHR 288                            // 8 consumer warps + 1 producer warp

// Device scratch (no allocations allowed)
// g_nf2 layout: [kblock][row][64 bf16], SW128 swizzle baked per 128B row:
// 16B group g of row r lives at byte r*128 + ((g ^ (r & 7)) * 16).
__device__ __align__(16) __nv_bfloat16 g_nf2[(size_t)KB_TOT * NROWS * BK];
__device__ int      g_k;
__device__ float    g_sumsq;
__device__ unsigned g_tile_cnt[NPAIR];
__device__ unsigned g_pairs_done;
__device__ float    g_part[NPAIR * SPLITS][TBM * TBM];  // split-K partial tiles

// ---------------- mbarrier / bulk-copy helpers (base sm_90 PTX) ----------------
#define MBAR_INIT(addr, cnt) \
    asm volatile("mbarrier.init.shared.b64 [%0], %1;" :: "r"(addr), "r"(cnt) : "memory")

#define MBAR_ARRIVE_EXPECT(addr, bytes) \
    asm volatile("mbarrier.arrive.expect_tx.shared.b64 _, [%0], %1;" \
                 :: "r"(addr), "r"(bytes) : "memory")

#define MBAR_ARRIVE(addr) \
    asm volatile("mbarrier.arrive.release.cta.shared::cta.b64 _, [%0];" \
                 :: "r"(addr) : "memory")

#define MBAR_WAIT(addr, parity) do {                                              \
    asm volatile("{\n\t.reg .pred P1;\n\t"                                        \
        "WL%=:\n\t"                                                               \
        "mbarrier.try_wait.parity.acquire.cta.shared::cta.b64 P1, [%0], %1, 0x989680;\n\t" \
        "@P1 bra.uni WD%=;\n\t"                                                   \
        "bra.uni WL%=;\n\t"                                                       \
        "WD%=:\n\t}"                                                              \
        :: "r"(addr), "r"(parity) : "memory");                                    \
} while (0)

#define BULK_G2S(dst, src, bytes, mbar) \
    asm volatile("cp.async.bulk.shared::cta.global.mbarrier::complete_tx::bytes " \
                 "[%0], [%1], %2, [%3];" \
                 :: "r"(dst), "l"(src), "r"(bytes), "r"(mbar) : "memory")

// ---------------------------------------------------------------------------
// Kernel 1: per-row normalize + inline mask scan + pad-row zeroing.
// Writes g_nf2 in k-block-major, swizzle-baked layout.
// ---------------------------------------------------------------------------
__global__ void __launch_bounds__(256) normalize_kernel(const float* __restrict__ w,
                                                        const float* __restrict__ mask,
                                                        float* __restrict__ out) {
    __shared__ int s_cnt[32];
    __shared__ int s_posk[2];
    int row = blockIdx.x;
    int tid = threadIdx.x;
    int lane = tid & 31, wid = tid >> 5;
    const unsigned full = 0xffffffffu;

    // inline scan: each thread owns mask[8t .. 8t+7]
    const float4* m4 = (const float4*)mask;
    float4 ma = m4[2 * tid], mb = m4[2 * tid + 1];
    int c8 = (ma.x > 0.5f) + (ma.y > 0.5f) + (ma.z > 0.5f) + (ma.w > 0.5f)
           + (mb.x > 0.5f) + (mb.y > 0.5f) + (mb.z > 0.5f) + (mb.w > 0.5f);
    int incl = c8;
#pragma unroll
    for (int o = 1; o < 32; o <<= 1) {
        int v = __shfl_up_sync(full, incl, o);
        if (lane >= o) incl += v;
    }
    if (lane == 31) s_cnt[wid] = incl;
    __syncthreads();
    if (wid == 0) {
        int iv = (lane < 8) ? s_cnt[lane] : 0;
#pragma unroll
        for (int o = 1; o < 8; o <<= 1) {
            int u = __shfl_up_sync(full, iv, o);
            if (lane >= o) iv += u;
        }
        if (lane < 8) s_cnt[lane] = iv;
    }
    __syncthreads();
    if (tid == (row >> 3)) {
        int exclWarp = (wid > 0) ? s_cnt[wid - 1] : 0;
        int excl8 = exclWarp + incl - c8;
        int base = row & ~7;
        int p = excl8;
        bool act = false;
#pragma unroll
        for (int q = 0; q < 8; q++) {
            int rr = base + q;
            bool a = mask[rr] > 0.5f;
            if (rr < row) p += a;
            else if (rr == row) act = a;
        }
        s_posk[0] = act ? p : -(row - p) - 1;   // inactive: encode inactive index
        s_posk[1] = s_cnt[7];
    }
    __syncthreads();
    int pos = s_posk[0];
    int k   = s_posk[1];

    if (row == 0 && tid < NPAIR) g_tile_cnt[tid] = 0u;
    if (row == 0 && tid == 0) {
        g_k = k; g_sumsq = 0.0f; g_pairs_done = 0u;
        if (k < 2) out[0] = 0.0f;
    }

    uint2* nf2 = (uint2*)g_nf2;   // 8B units; per kb block = NROWS*16 uint2

    if (pos < 0) {
        // zero pad rows [k, ceil(k/128)*128) so gram tiles see exact zeros
        int padIdx = -pos - 1;
        int T = (k + TBM - 1) >> 7;
        int padRows = T * TBM - k;
        if (padIdx < padRows) {
            int prow = k + padIdx;
            uint2 z = make_uint2(0u, 0u);
#pragma unroll
            for (int i = 0; i < 9; i++) {
                int c = tid + i * 256;            // 8B chunk index 0..2303
                int kb = c >> 4, rem = c & 15;
                int g16 = rem >> 1, half = rem & 1;
                size_t idx = (size_t)kb * (NROWS * 16) + (size_t)prow * 16
                           + ((g16 ^ (prow & 7)) << 1) + half;
                nf2[idx] = z;
            }
        }
        return;
    }

    const float4* src = (const float4*)(w + (size_t)row * DDIM);
    float4 v[9];
    float sum = 0.0f, sumsq = 0.0f;
#pragma unroll
    for (int i = 0; i < 9; i++) {
        v[i] = src[tid + i * 256];
        sum   += v[i].x + v[i].y + v[i].z + v[i].w;
        sumsq += v[i].x * v[i].x + v[i].y * v[i].y + v[i].z * v[i].z + v[i].w * v[i].w;
    }

    __shared__ float rs[256], rq[256];
    rs[tid] = sum; rq[tid] = sumsq;
    __syncthreads();
    for (int o = 128; o > 0; o >>= 1) {
        if (tid < o) { rs[tid] += rs[tid + o]; rq[tid] += rq[tid + o]; }
        __syncthreads();
    }
    __shared__ float s_mean, s_inv;
    if (tid == 0) {
        float mean = rs[0] * (1.0f / DDIM);
        float var  = fmaxf(rq[0] * (1.0f / DDIM) - mean * mean, 0.0f);
        float stdv = sqrtf(var);
        s_mean = mean;
        s_inv  = (stdv == 0.0f) ? 1.0f : (1.0f / stdv);
    }
    __syncthreads();
    float mean = s_mean, inv = s_inv;

#pragma unroll
    for (int i = 0; i < 9; i++) {
        __nv_bfloat162 lo = __floats2bfloat162_rn((v[i].x - mean) * inv, (v[i].y - mean) * inv);
        __nv_bfloat162 hi = __floats2bfloat162_rn((v[i].z - mean) * inv, (v[i].w - mean) * inv);
        uint2 o;
        o.x = *(uint32_t*)&lo;
        o.y = *(uint32_t*)&hi;
        int c = tid + i * 256;                // 8B chunk index (4 bf16)
        int kb = c >> 4, rem = c & 15;
        int g16 = rem >> 1, half = rem & 1;
        size_t idx = (size_t)kb * (NROWS * 16) + (size_t)pos * 16
                   + ((g16 ^ (pos & 7)) << 1) + half;
        nf2[idx] = o;
    }
}

// ---------------------------------------------------------------------------
// Kernel 2: 128x128 bf16 Gram via mma.sync, split-K=4, WARP-SPECIALIZED:
// 8 consumer warps (32x64 tiles, fragment double-buffer) + 1 producer warp
// that owns all empty-waits + cp.async.bulk issues. Consumers never stall on
// backpressure; kk=3 MMAs fire before the next-stage full-wait.
// Last split combines partials + squares + finalizes.
// ---------------------------------------------------------------------------
__global__ void __launch_bounds__(NTHR, 1) gram_kernel(float* __restrict__ out) {
    extern __shared__ __align__(16) char smem[];
    __shared__ __align__(8) unsigned long long s_mbar[2 * STAGES];  // [full | empty]
    __shared__ float s_red[8];
    __shared__ unsigned s_prev;

    int k = g_k;
    int blk = blockIdx.x;
    int pair = blk >> 2;
    int split = blk & 3;
    int bi = 0, rem = pair;
    while (rem >= T16 - bi) { rem -= T16 - bi; bi++; }
    int bj = bi + rem;
    if (bj * TBM >= k) return;   // inactive tile

    int tid = threadIdx.x, lane = tid & 31, warp = tid >> 5;
    int wm = warp & 3;   // 0..3 : 32-row strip (consumers)
    int wn = warp >> 2;  // 0..1 : 64-col strip

    uint32_t sb  = (uint32_t)__cvta_generic_to_shared(smem);
    uint32_t mb0 = (uint32_t)__cvta_generic_to_shared(&s_mbar[0]);
    uint32_t me0 = mb0 + 8 * STAGES;
    if (tid < STAGES)          MBAR_INIT(mb0 + 8 * tid, 1);             // full: tx
    else if (tid < 2 * STAGES) MBAR_INIT(me0 + 8 * (tid - STAGES), 8);  // empty: 8 consumers
    __syncthreads();   // barriers visible before any use

    const char* nfb = (const char*)g_nf2;
    int kb0 = split * NIT;   // first k-block of this split

    if (warp == 8) {
        // ---------------- producer warp ----------------
        if (lane == 0) {
            // prologue + mainloop issue, gated by empty-barrier backpressure
            for (int jl = 0; jl < NIT; jl++) {
                int js = jl & (STAGES - 1);
                int jr = jl >> 2;
                if (jr >= 1) MBAR_WAIT(me0 + 8 * js, (jr - 1) & 1);  // slot drained
                uint32_t m = mb0 + 8 * js;
                size_t kbOff = (size_t)(kb0 + jl) * ((size_t)NROWS * 128);
                const char* srcA = nfb + kbOff + (size_t)(bi * TBM) * 128;
                const char* srcB = nfb + kbOff + (size_t)(bj * TBM) * 128;
                MBAR_ARRIVE_EXPECT(m, STAGE_BYTES);
                BULK_G2S(sb + js * STAGE_BYTES,           srcA, OPBYTES, m);
                BULK_G2S(sb + js * STAGE_BYTES + OPBYTES, srcB, OPBYTES, m);
            }
        }
    } else {
        // ---------------- consumer warps ----------------
        float acc[2][8][4];
#pragma unroll
        for (int mt = 0; mt < 2; mt++)
#pragma unroll
            for (int n = 0; n < 8; n++)
#pragma unroll
                for (int e = 0; e < 4; e++) acc[mt][n][e] = 0.0f;

        // fixed per-warp fragment addressing (SW128 swizzle pre-baked in gmem)
        int raBase = wm * 32 + (lane & 15);                 // A rows; mt adds +16
        int gaSel  = lane >> 4;                             // A k-half within k16
        int rbBase = wn * 64 + (lane & 7) + ((lane >> 4) << 3);  // B rows; nt +16
        int gbSel  = (lane >> 3) & 1;                       // B k-half within k16

        uint32_t af[2][2][4];
        uint32_t bf[2][4][4];

#define LD_FRAGS(buf, aB_, bB_, kk_) do {                                         \
    _Pragma("unroll")                                                             \
    for (int mt = 0; mt < 2; mt++) {                                              \
        int r = raBase + mt * 16;                                                 \
        int g = (kk_) * 2 + gaSel;                                                \
        uint32_t addr = (aB_) + (uint32_t)(r * 128 + ((g ^ (r & 7)) << 4));       \
        asm volatile("ldmatrix.sync.aligned.m8n8.x4.shared.b16 {%0,%1,%2,%3}, [%4];\n" \
                     : "=r"(af[buf][mt][0]), "=r"(af[buf][mt][1]),                \
                       "=r"(af[buf][mt][2]), "=r"(af[buf][mt][3])                 \
                     : "r"(addr));                                                \
    }                                                                             \
    _Pragma("unroll")                                                             \
    for (int nt = 0; nt < 4; nt++) {                                              \
        int r = rbBase + nt * 16;                                                 \
        int g = (kk_) * 2 + gbSel;                                                \
        uint32_t addr = (bB_) + (uint32_t)(r * 128 + ((g ^ (r & 7)) << 4));       \
        asm volatile("ldmatrix.sync.aligned.m8n8.x4.shared.b16 {%0,%1,%2,%3}, [%4];\n" \
                     : "=r"(bf[buf][nt][0]), "=r"(bf[buf][nt][1]),                \
                       "=r"(bf[buf][nt][2]), "=r"(bf[buf][nt][3])                 \
                     : "r"(addr));                                                \
    }                                                                             \
} while (0)

#define DO_MMAS(cb_) do {                                                         \
    _Pragma("unroll")                                                             \
    for (int mt = 0; mt < 2; mt++)                                                \
        _Pragma("unroll")                                                         \
        for (int nt = 0; nt < 4; nt++)                                            \
            _Pragma("unroll")                                                     \
            for (int h = 0; h < 2; h++) {                                         \
                asm volatile(                                                     \
                    "mma.sync.aligned.m16n8k16.row.col.f32.bf16.bf16.f32 "        \
                    "{%0,%1,%2,%3}, {%4,%5,%6,%7}, {%8,%9}, {%0,%1,%2,%3};\n"     \
                    : "+f"(acc[mt][nt * 2 + h][0]), "+f"(acc[mt][nt * 2 + h][1]), \
                      "+f"(acc[mt][nt * 2 + h][2]), "+f"(acc[mt][nt * 2 + h][3])  \
                    : "r"(af[cb_][mt][0]), "r"(af[cb_][mt][1]),                   \
                      "r"(af[cb_][mt][2]), "r"(af[cb_][mt][3]),                   \
                      "r"(bf[cb_][nt][h * 2]), "r"(bf[cb_][nt][h * 2 + 1]));      \
            }                                                                     \
} while (0)

        // initial: wait stage 0, preload frags for (it=0, kk=0) into buf 0
        MBAR_WAIT(mb0 + 0, 0);
        LD_FRAGS(0, sb, sb + OPBYTES, 0);

        int slot = 0;
        for (int it = 0; it < NIT; it++) {
            uint32_t aB = sb + slot * STAGE_BYTES, bB = aB + OPBYTES;
            int nslot = (slot + 1) & (STAGES - 1);
            uint32_t aBn = sb + nslot * STAGE_BYTES, bBn = aBn + OPBYTES;

            // kk = 0..2: prefetch next-step frags, then MMA on current buffer
#pragma unroll
            for (int kk = 0; kk < 3; kk++) {
                const int cb = kk & 1, nb = cb ^ 1;
                LD_FRAGS(nb, aB, bB, kk + 1);
                DO_MMAS(cb);
            }
            // done reading `slot` (kk=3 frags already in regs from kk=2)
            if (lane == 0) MBAR_ARRIVE(me0 + 8 * slot);
            // kk = 3: MMAs FIRST, then wait next stage + prefetch its kk=0
            DO_MMAS(1);
            if (it + 1 < NIT) {
                MBAR_WAIT(mb0 + 8 * nslot, ((it + 1) >> 2) & 1);
                LD_FRAGS(0, aBn, bBn, 0);
            }
            slot = nslot;
        }
#undef LD_FRAGS
#undef DO_MMAS

        // write split-partial tile (plain float2 stores, no atomics)
        float* part = g_part[pair * SPLITS + split];
#pragma unroll
        for (int mt = 0; mt < 2; mt++)
#pragma unroll
            for (int nt = 0; nt < 4; nt++)
#pragma unroll
                for (int h = 0; h < 2; h++) {
                    int r0 = wm * 32 + mt * 16 + (lane >> 2);
                    int c  = wn * 64 + nt * 16 + h * 8 + ((lane & 3) << 1);
                    float* a4 = acc[mt][nt * 2 + h];
                    *(float2*)(part + r0 * TBM + c)       = make_float2(a4[0], a4[1]);
                    *(float2*)(part + (r0 + 8) * TBM + c) = make_float2(a4[2], a4[3]);
                }
    }

    __threadfence();   // publish partial tile
    __syncthreads();
    if (tid == 0) s_prev = atomicAdd(&g_tile_cnt[pair], 1u);
    __syncthreads();

    if (s_prev == SPLITS - 1) {   // last split: combine, square, accumulate
        __threadfence();
        const float invD = 1.0f / (float)DDIM;
        const float* pbase = g_part[pair * SPLITS];
        float ss = 0.0f;
        if (warp < 8) {
            for (int idx = tid; idx < TBM * TBM; idx += 256) {
                float v = 0.0f;
#pragma unroll
                for (int sp = 0; sp < SPLITS; sp++)
                    v += pbase[sp * TBM * TBM + idx];
                int r = idx >> 7, c = idx & 127;
                int gi = bi * TBM + r, gj = bj * TBM + c;
                if (gi < gj) {   // pad rows/cols are exact zeros
                    v *= invD;
                    ss += v * v;
                }
            }
        }
#pragma unroll
        for (int o = 16; o > 0; o >>= 1) ss += __shfl_xor_sync(0xffffffffu, ss, o);
        if (lane == 0 && warp < 8) s_red[warp] = ss;
        __syncthreads();
        if (tid == 0) {
            float bs = 0.0f;
#pragma unroll
            for (int w2 = 0; w2 < 8; w2++) bs += s_red[w2];
            atomicAdd(&g_sumsq, bs);
            __threadfence();
            unsigned p = atomicAdd(&g_pairs_done, 1u);
            int T = (k + TBM - 1) / TBM;
            unsigned tot = (unsigned)(T * (T + 1) / 2);
            if (p == tot - 1) {   // last tile overall: write the loss
                float total = atomicAdd(&g_sumsq, 0.0f);
                long long np = (long long)k * (k - 1) / 2;
                out[0] = (np > 0) ? (total / (float)np) : 0.0f;
            }
        }
    }
}

extern "C" void kernel_launch(void* const* d_in, const int* in_sizes, int n_in,
                              void* d_out, int out_size) {
    const float* w    = (const float*)d_in[0];  // [2048,1024,3,3] fp32
    const float* mask = (const float*)d_in[1];  // [2048,1,1,1]   fp32
    float* out = (float*)d_out;

    static bool attr_set = false;
    if (!attr_set) {
        cudaFuncSetAttribute(gram_kernel,
                             cudaFuncAttributeMaxDynamicSharedMemorySize, DSMEM_BYTES);
        attr_set = true;
    }

    normalize_kernel<<<NROWS, 256>>>(w, mask, out);
    gram_kernel<<<NPAIR * SPLITS, NTHR, DSMEM_BYTES>>>(out);
}

// round 14
// speedup vs baseline: 1.2252x; 1.0095x over previous
#include <cuda_runtime.h>
#include <cuda_bf16.h>
#include <cstdint>

// Problem constants
#define NROWS 2048
#define DDIM  9216             // C*KH*KW
#define TBM   128              // gram tile M = N = 128
#define T16   (NROWS / TBM)    // 16 tiles per dim (max)
#define NPAIR (T16 * (T16 + 1) / 2)   // 136 tile-pairs
#define SPLITS 4
#define KCH   (DDIM / SPLITS)  // 2304 k-elems per split
#define BK    64               // k-elems per pipeline stage (one k-block)
#define NIT   (KCH / BK)       // 36 iterations
#define KB_TOT (DDIM / BK)     // 144 k-blocks
#define STAGES 4
#define OPBYTES (TBM * 128)                 // 16 KB per operand per stage
#define STAGE_BYTES (2 * OPBYTES)           // 32 KB
#define DSMEM_BYTES (STAGES * STAGE_BYTES)  // 128 KB
#define NTHR 544                            // 16 consumer warps + 1 producer warp

// Device scratch (no allocations allowed)
// g_nf2 layout: [kblock][row][64 bf16], SW128 swizzle baked per 128B row:
// 16B group g of row r lives at byte r*128 + ((g ^ (r & 7)) * 16).
__device__ __align__(16) __nv_bfloat16 g_nf2[(size_t)KB_TOT * NROWS * BK];
__device__ int      g_k;
__device__ float    g_sumsq;
__device__ unsigned g_tile_cnt[NPAIR];
__device__ unsigned g_pairs_done;
__device__ float    g_part[NPAIR * SPLITS][TBM * TBM];  // split-K partial tiles

// ---------------- mbarrier / bulk-copy helpers (base sm_90 PTX) ----------------
#define MBAR_INIT(addr, cnt) \
    asm volatile("mbarrier.init.shared.b64 [%0], %1;" :: "r"(addr), "r"(cnt) : "memory")

#define MBAR_ARRIVE_EXPECT(addr, bytes) \
    asm volatile("mbarrier.arrive.expect_tx.shared.b64 _, [%0], %1;" \
                 :: "r"(addr), "r"(bytes) : "memory")

#define MBAR_ARRIVE(addr) \
    asm volatile("mbarrier.arrive.release.cta.shared::cta.b64 _, [%0];" \
                 :: "r"(addr) : "memory")

#define MBAR_WAIT(addr, parity) do {                                              \
    asm volatile("{\n\t.reg .pred P1;\n\t"                                        \
        "WL%=:\n\t"                                                               \
        "mbarrier.try_wait.parity.acquire.cta.shared::cta.b64 P1, [%0], %1, 0x989680;\n\t" \
        "@P1 bra.uni WD%=;\n\t"                                                   \
        "bra.uni WL%=;\n\t"                                                       \
        "WD%=:\n\t}"                                                              \
        :: "r"(addr), "r"(parity) : "memory");                                    \
} while (0)

#define BULK_G2S(dst, src, bytes, mbar) \
    asm volatile("cp.async.bulk.shared::cta.global.mbarrier::complete_tx::bytes " \
                 "[%0], [%1], %2, [%3];" \
                 :: "r"(dst), "l"(src), "r"(bytes), "r"(mbar) : "memory")

// ---------------------------------------------------------------------------
// Kernel 1: per-row normalize + inline mask scan + pad-row zeroing.
// Writes g_nf2 in k-block-major, swizzle-baked layout.
// ---------------------------------------------------------------------------
__global__ void __launch_bounds__(256) normalize_kernel(const float* __restrict__ w,
                                                        const float* __restrict__ mask,
                                                        float* __restrict__ out) {
    __shared__ int s_cnt[32];
    __shared__ int s_posk[2];
    int row = blockIdx.x;
    int tid = threadIdx.x;
    int lane = tid & 31, wid = tid >> 5;
    const unsigned full = 0xffffffffu;

    // inline scan: each thread owns mask[8t .. 8t+7]
    const float4* m4 = (const float4*)mask;
    float4 ma = m4[2 * tid], mb = m4[2 * tid + 1];
    int c8 = (ma.x > 0.5f) + (ma.y > 0.5f) + (ma.z > 0.5f) + (ma.w > 0.5f)
           + (mb.x > 0.5f) + (mb.y > 0.5f) + (mb.z > 0.5f) + (mb.w > 0.5f);
    int incl = c8;
#pragma unroll
    for (int o = 1; o < 32; o <<= 1) {
        int v = __shfl_up_sync(full, incl, o);
        if (lane >= o) incl += v;
    }
    if (lane == 31) s_cnt[wid] = incl;
    __syncthreads();
    if (wid == 0) {
        int iv = (lane < 8) ? s_cnt[lane] : 0;
#pragma unroll
        for (int o = 1; o < 8; o <<= 1) {
            int u = __shfl_up_sync(full, iv, o);
            if (lane >= o) iv += u;
        }
        if (lane < 8) s_cnt[lane] = iv;
    }
    __syncthreads();
    if (tid == (row >> 3)) {
        int exclWarp = (wid > 0) ? s_cnt[wid - 1] : 0;
        int excl8 = exclWarp + incl - c8;
        int base = row & ~7;
        int p = excl8;
        bool act = false;
#pragma unroll
        for (int q = 0; q < 8; q++) {
            int rr = base + q;
            bool a = mask[rr] > 0.5f;
            if (rr < row) p += a;
            else if (rr == row) act = a;
        }
        s_posk[0] = act ? p : -(row - p) - 1;   // inactive: encode inactive index
        s_posk[1] = s_cnt[7];
    }
    __syncthreads();
    int pos = s_posk[0];
    int k   = s_posk[1];

    if (row == 0 && tid < NPAIR) g_tile_cnt[tid] = 0u;
    if (row == 0 && tid == 0) {
        g_k = k; g_sumsq = 0.0f; g_pairs_done = 0u;
        if (k < 2) out[0] = 0.0f;
    }

    uint2* nf2 = (uint2*)g_nf2;   // 8B units; per kb block = NROWS*16 uint2

    if (pos < 0) {
        // zero pad rows [k, ceil(k/128)*128) so gram tiles see exact zeros
        int padIdx = -pos - 1;
        int T = (k + TBM - 1) >> 7;
        int padRows = T * TBM - k;
        if (padIdx < padRows) {
            int prow = k + padIdx;
            uint2 z = make_uint2(0u, 0u);
#pragma unroll
            for (int i = 0; i < 9; i++) {
                int c = tid + i * 256;            // 8B chunk index 0..2303
                int kb = c >> 4, rem = c & 15;
                int g16 = rem >> 1, half = rem & 1;
                size_t idx = (size_t)kb * (NROWS * 16) + (size_t)prow * 16
                           + ((g16 ^ (prow & 7)) << 1) + half;
                nf2[idx] = z;
            }
        }
        return;
    }

    const float4* src = (const float4*)(w + (size_t)row * DDIM);
    float4 v[9];
    float sum = 0.0f, sumsq = 0.0f;
#pragma unroll
    for (int i = 0; i < 9; i++) {
        v[i] = src[tid + i * 256];
        sum   += v[i].x + v[i].y + v[i].z + v[i].w;
        sumsq += v[i].x * v[i].x + v[i].y * v[i].y + v[i].z * v[i].z + v[i].w * v[i].w;
    }

    __shared__ float rs[256], rq[256];
    rs[tid] = sum; rq[tid] = sumsq;
    __syncthreads();
    for (int o = 128; o > 0; o >>= 1) {
        if (tid < o) { rs[tid] += rs[tid + o]; rq[tid] += rq[tid + o]; }
        __syncthreads();
    }
    __shared__ float s_mean, s_inv;
    if (tid == 0) {
        float mean = rs[0] * (1.0f / DDIM);
        float var  = fmaxf(rq[0] * (1.0f / DDIM) - mean * mean, 0.0f);
        float stdv = sqrtf(var);
        s_mean = mean;
        s_inv  = (stdv == 0.0f) ? 1.0f : (1.0f / stdv);
    }
    __syncthreads();
    float mean = s_mean, inv = s_inv;

#pragma unroll
    for (int i = 0; i < 9; i++) {
        __nv_bfloat162 lo = __floats2bfloat162_rn((v[i].x - mean) * inv, (v[i].y - mean) * inv);
        __nv_bfloat162 hi = __floats2bfloat162_rn((v[i].z - mean) * inv, (v[i].w - mean) * inv);
        uint2 o;
        o.x = *(uint32_t*)&lo;
        o.y = *(uint32_t*)&hi;
        int c = tid + i * 256;                // 8B chunk index (4 bf16)
        int kb = c >> 4, rem = c & 15;
        int g16 = rem >> 1, half = rem & 1;
        size_t idx = (size_t)kb * (NROWS * 16) + (size_t)pos * 16
                   + ((g16 ^ (pos & 7)) << 1) + half;
        nf2[idx] = o;
    }
}

// ---------------------------------------------------------------------------
// Kernel 2: 128x128 bf16 Gram via mma.sync, split-K=4, WARP-SPECIALIZED:
// 16 consumer warps (4x4 grid of 32x32 tiles, fragment double-buffer; ~4
// warps per SMSP hide LDSM/dependency windows under other warps' MMA bursts)
// + 1 producer warp owning all empty-waits + cp.async.bulk issues.
// Last split combines partials + squares + finalizes.
// ---------------------------------------------------------------------------
__global__ void __launch_bounds__(NTHR, 1) gram_kernel(float* __restrict__ out) {
    extern __shared__ __align__(16) char smem[];
    __shared__ __align__(8) unsigned long long s_mbar[2 * STAGES];  // [full | empty]
    __shared__ float s_red[16];
    __shared__ unsigned s_prev;

    int k = g_k;
    int blk = blockIdx.x;
    int pair = blk >> 2;
    int split = blk & 3;
    int bi = 0, rem = pair;
    while (rem >= T16 - bi) { rem -= T16 - bi; bi++; }
    int bj = bi + rem;
    if (bj * TBM >= k) return;   // inactive tile

    int tid = threadIdx.x, lane = tid & 31, warp = tid >> 5;
    int wm = warp & 3;   // 0..3 : 32-row strip (consumers)
    int wn = warp >> 2;  // 0..3 : 32-col strip

    uint32_t sb  = (uint32_t)__cvta_generic_to_shared(smem);
    uint32_t mb0 = (uint32_t)__cvta_generic_to_shared(&s_mbar[0]);
    uint32_t me0 = mb0 + 8 * STAGES;
    if (tid < STAGES)          MBAR_INIT(mb0 + 8 * tid, 1);              // full: tx
    else if (tid < 2 * STAGES) MBAR_INIT(me0 + 8 * (tid - STAGES), 16);  // empty: 16
    __syncthreads();   // barriers visible before any use

    const char* nfb = (const char*)g_nf2;
    int kb0 = split * NIT;   // first k-block of this split

    if (warp == 16) {
        // ---------------- producer warp ----------------
        if (lane == 0) {
            for (int jl = 0; jl < NIT; jl++) {
                int js = jl & (STAGES - 1);
                int jr = jl >> 2;
                if (jr >= 1) MBAR_WAIT(me0 + 8 * js, (jr - 1) & 1);  // slot drained
                uint32_t m = mb0 + 8 * js;
                size_t kbOff = (size_t)(kb0 + jl) * ((size_t)NROWS * 128);
                const char* srcA = nfb + kbOff + (size_t)(bi * TBM) * 128;
                const char* srcB = nfb + kbOff + (size_t)(bj * TBM) * 128;
                MBAR_ARRIVE_EXPECT(m, STAGE_BYTES);
                BULK_G2S(sb + js * STAGE_BYTES,           srcA, OPBYTES, m);
                BULK_G2S(sb + js * STAGE_BYTES + OPBYTES, srcB, OPBYTES, m);
            }
        }
    } else {
        // ---------------- consumer warps (32x32 tile each) ----------------
        float acc[2][4][4];   // [mt][nt*2+h][4]
#pragma unroll
        for (int mt = 0; mt < 2; mt++)
#pragma unroll
            for (int n = 0; n < 4; n++)
#pragma unroll
                for (int e = 0; e < 4; e++) acc[mt][n][e] = 0.0f;

        // fixed per-warp fragment addressing (SW128 swizzle pre-baked in gmem)
        int raBase = wm * 32 + (lane & 15);                 // A rows; mt adds +16
        int gaSel  = lane >> 4;                             // A k-half within k16
        int rbBase = wn * 32 + (lane & 7) + ((lane >> 4) << 3);  // B rows; nt +16
        int gbSel  = (lane >> 3) & 1;                       // B k-half within k16

        uint32_t af[2][2][4];
        uint32_t bf[2][2][4];

#define LD_FRAGS(buf, aB_, bB_, kk_) do {                                         \
    _Pragma("unroll")                                                             \
    for (int mt = 0; mt < 2; mt++) {                                              \
        int r = raBase + mt * 16;                                                 \
        int g = (kk_) * 2 + gaSel;                                                \
        uint32_t addr = (aB_) + (uint32_t)(r * 128 + ((g ^ (r & 7)) << 4));       \
        asm volatile("ldmatrix.sync.aligned.m8n8.x4.shared.b16 {%0,%1,%2,%3}, [%4];\n" \
                     : "=r"(af[buf][mt][0]), "=r"(af[buf][mt][1]),                \
                       "=r"(af[buf][mt][2]), "=r"(af[buf][mt][3])                 \
                     : "r"(addr));                                                \
    }                                                                             \
    _Pragma("unroll")                                                             \
    for (int nt = 0; nt < 2; nt++) {                                              \
        int r = rbBase + nt * 16;                                                 \
        int g = (kk_) * 2 + gbSel;                                                \
        uint32_t addr = (bB_) + (uint32_t)(r * 128 + ((g ^ (r & 7)) << 4));       \
        asm volatile("ldmatrix.sync.aligned.m8n8.x4.shared.b16 {%0,%1,%2,%3}, [%4];\n" \
                     : "=r"(bf[buf][nt][0]), "=r"(bf[buf][nt][1]),                \
                       "=r"(bf[buf][nt][2]), "=r"(bf[buf][nt][3])                 \
                     : "r"(addr));                                                \
    }                                                                             \
} while (0)

#define DO_MMAS(cb_) do {                                                         \
    _Pragma("unroll")                                                             \
    for (int mt = 0; mt < 2; mt++)                                                \
        _Pragma("unroll")                                                         \
        for (int nt = 0; nt < 2; nt++)                                            \
            _Pragma("unroll")                                                     \
            for (int h = 0; h < 2; h++) {                                         \
                asm volatile(                                                     \
                    "mma.sync.aligned.m16n8k16.row.col.f32.bf16.bf16.f32 "        \
                    "{%0,%1,%2,%3}, {%4,%5,%6,%7}, {%8,%9}, {%0,%1,%2,%3};\n"     \
                    : "+f"(acc[mt][nt * 2 + h][0]), "+f"(acc[mt][nt * 2 + h][1]), \
                      "+f"(acc[mt][nt * 2 + h][2]), "+f"(acc[mt][nt * 2 + h][3])  \
                    : "r"(af[cb_][mt][0]), "r"(af[cb_][mt][1]),                   \
                      "r"(af[cb_][mt][2]), "r"(af[cb_][mt][3]),                   \
                      "r"(bf[cb_][nt][h * 2]), "r"(bf[cb_][nt][h * 2 + 1]));      \
            }                                                                     \
} while (0)

        // initial: wait stage 0, preload frags for (it=0, kk=0) into buf 0
        MBAR_WAIT(mb0 + 0, 0);
        LD_FRAGS(0, sb, sb + OPBYTES, 0);

        int slot = 0;
        for (int it = 0; it < NIT; it++) {
            uint32_t aB = sb + slot * STAGE_BYTES, bB = aB + OPBYTES;
            int nslot = (slot + 1) & (STAGES - 1);
            uint32_t aBn = sb + nslot * STAGE_BYTES, bBn = aBn + OPBYTES;

            // kk = 0..2: prefetch next-step frags, then MMA on current buffer
#pragma unroll
            for (int kk = 0; kk < 3; kk++) {
                const int cb = kk & 1, nb = cb ^ 1;
                LD_FRAGS(nb, aB, bB, kk + 1);
                DO_MMAS(cb);
            }
            // done reading `slot` (kk=3 frags already in regs from kk=2)
            if (lane == 0) MBAR_ARRIVE(me0 + 8 * slot);
            // kk = 3: MMAs FIRST, then wait next stage + prefetch its kk=0
            DO_MMAS(1);
            if (it + 1 < NIT) {
                MBAR_WAIT(mb0 + 8 * nslot, ((it + 1) >> 2) & 1);
                LD_FRAGS(0, aBn, bBn, 0);
            }
            slot = nslot;
        }
#undef LD_FRAGS
#undef DO_MMAS

        // write split-partial tile (plain float2 stores, no atomics)
        float* part = g_part[pair * SPLITS + split];
#pragma unroll
        for (int mt = 0; mt < 2; mt++)
#pragma unroll
            for (int nt = 0; nt < 2; nt++)
#pragma unroll
                for (int h = 0; h < 2; h++) {
                    int r0 = wm * 32 + mt * 16 + (lane >> 2);
                    int c  = wn * 32 + nt * 16 + h * 8 + ((lane & 3) << 1);
                    float* a4 = acc[mt][nt * 2 + h];
                    *(float2*)(part + r0 * TBM + c)       = make_float2(a4[0], a4[1]);
                    *(float2*)(part + (r0 + 8) * TBM + c) = make_float2(a4[2], a4[3]);
                }
    }

    __threadfence();   // publish partial tile
    __syncthreads();
    if (tid == 0) s_prev = atomicAdd(&g_tile_cnt[pair], 1u);
    __syncthreads();

    if (s_prev == SPLITS - 1) {   // last split: combine, square, accumulate
        __threadfence();
        const float invD = 1.0f / (float)DDIM;
        const float* pbase = g_part[pair * SPLITS];
        float ss = 0.0f;
        if (warp < 16) {
            for (int idx = tid; idx < TBM * TBM; idx += 512) {
                float v = 0.0f;
#pragma unroll
                for (int sp = 0; sp < SPLITS; sp++)
                    v += pbase[sp * TBM * TBM + idx];
                int r = idx >> 7, c = idx & 127;
                int gi = bi * TBM + r, gj = bj * TBM + c;
                if (gi < gj) {   // pad rows/cols are exact zeros
                    v *= invD;
                    ss += v * v;
                }
            }
        }
#pragma unroll
        for (int o = 16; o > 0; o >>= 1) ss += __shfl_xor_sync(0xffffffffu, ss, o);
        if (lane == 0 && warp < 16) s_red[warp] = ss;
        __syncthreads();
        if (tid == 0) {
            float bs = 0.0f;
#pragma unroll
            for (int w2 = 0; w2 < 16; w2++) bs += s_red[w2];
            atomicAdd(&g_sumsq, bs);
            __threadfence();
            unsigned p = atomicAdd(&g_pairs_done, 1u);
            int T = (k + TBM - 1) / TBM;
            unsigned tot = (unsigned)(T * (T + 1) / 2);
            if (p == tot - 1) {   // last tile overall: write the loss
                float total = atomicAdd(&g_sumsq, 0.0f);
                long long np = (long long)k * (k - 1) / 2;
                out[0] = (np > 0) ? (total / (float)np) : 0.0f;
            }
        }
    }
}

extern "C" void kernel_launch(void* const* d_in, const int* in_sizes, int n_in,
                              void* d_out, int out_size) {
    const float* w    = (const float*)d_in[0];  // [2048,1024,3,3] fp32
    const float* mask = (const float*)d_in[1];  // [2048,1,1,1]   fp32
    float* out = (float*)d_out;

    static bool attr_set = false;
    if (!attr_set) {
        cudaFuncSetAttribute(gram_kernel,
                             cudaFuncAttributeMaxDynamicSharedMemorySize, DSMEM_BYTES);
        attr_set = true;
    }

    normalize_kernel<<<NROWS, 256>>>(w, mask, out);
    gram_kernel<<<NPAIR * SPLITS, NTHR, DSMEM_BYTES>>>(out);
}